// round 1
// baseline (speedup 1.0000x reference)
#include <cuda_runtime.h>
#include <math.h>

// ---------------- problem constants ----------------
#define BB   4
#define NN   2048
#define EE   1024
#define HH   16
#define DD   64
#define HID  4096
#define MM   (BB * NN)          // 8192 rows

// ---------------- scratch (device globals; no allocation) ----------------
__device__ float g_qkv [(size_t)MM * 3 * EE];   // 8192 x 3072
__device__ float g_attn[(size_t)MM * EE];       // 8192 x 1024 (scrambled attn out)
__device__ float g_res1[(size_t)MM * EE];       // x + attn proj
__device__ float g_h   [(size_t)MM * EE];       // LN1 out
__device__ float g_ffn [(size_t)MM * HID];      // gelu(h W1^T + b)
__device__ float g_res2[(size_t)MM * EE];       // h + ffn proj

// ---------------- tiled fp32 NT GEMM: C = A[M,K] * B[N,K]^T + bias (+epi) ----------------
// EPI: 0 = bias only, 1 = bias + exact GELU, 2 = bias + residual add
template <int EPI>
__global__ __launch_bounds__(256) void gemm_nt(
    const float* __restrict__ A, const float* __restrict__ B,
    const float* __restrict__ bias, const float* __restrict__ res,
    float* __restrict__ C, int M, int N, int K)
{
    __shared__ float As[16][128];
    __shared__ float Bs[16][128];

    const int tid = threadIdx.x;
    const int tx  = tid & 15;        // 0..15 -> 8 cols each
    const int ty  = tid >> 4;        // 0..15 -> 8 rows each
    const int m0  = blockIdx.y * 128;
    const int n0  = blockIdx.x * 128;

    const int lrow = tid >> 2;       // 0..63
    const int lcol = (tid & 3) * 4;  // 0,4,8,12

    float acc[8][8];
#pragma unroll
    for (int i = 0; i < 8; ++i)
#pragma unroll
        for (int j = 0; j < 8; ++j) acc[i][j] = 0.f;

    for (int k0 = 0; k0 < K; k0 += 16) {
#pragma unroll
        for (int r = 0; r < 128; r += 64) {
            float4 av = *reinterpret_cast<const float4*>(
                &A[(size_t)(m0 + lrow + r) * K + k0 + lcol]);
            As[lcol + 0][lrow + r] = av.x;
            As[lcol + 1][lrow + r] = av.y;
            As[lcol + 2][lrow + r] = av.z;
            As[lcol + 3][lrow + r] = av.w;
            float4 bv = *reinterpret_cast<const float4*>(
                &B[(size_t)(n0 + lrow + r) * K + k0 + lcol]);
            Bs[lcol + 0][lrow + r] = bv.x;
            Bs[lcol + 1][lrow + r] = bv.y;
            Bs[lcol + 2][lrow + r] = bv.z;
            Bs[lcol + 3][lrow + r] = bv.w;
        }
        __syncthreads();
#pragma unroll
        for (int k = 0; k < 16; ++k) {
            float a[8], bb[8];
#pragma unroll
            for (int i = 0; i < 8; ++i) a[i] = As[k][ty * 8 + i];
#pragma unroll
            for (int j = 0; j < 8; ++j) bb[j] = Bs[k][tx * 8 + j];
#pragma unroll
            for (int i = 0; i < 8; ++i)
#pragma unroll
                for (int j = 0; j < 8; ++j) acc[i][j] += a[i] * bb[j];
        }
        __syncthreads();
    }

    // epilogue
#pragma unroll
    for (int i = 0; i < 8; ++i) {
        const int m = m0 + ty * 8 + i;
        float tmp[8];
#pragma unroll
        for (int j = 0; j < 8; ++j) {
            const int n = n0 + tx * 8 + j;
            float v = acc[i][j] + bias[n];
            if (EPI == 1) v = 0.5f * v * (1.0f + erff(v * 0.70710678118654752f));
            if (EPI == 2) v += res[(size_t)m * N + n];
            tmp[j] = v;
        }
        float* dst = &C[(size_t)m * N + n0 + tx * 8];
        *reinterpret_cast<float4*>(dst)     = make_float4(tmp[0], tmp[1], tmp[2], tmp[3]);
        *reinterpret_cast<float4*>(dst + 4) = make_float4(tmp[4], tmp[5], tmp[6], tmp[7]);
    }
}

// ---------------- per-token head-softmax attention + scrambled reshape ----------------
// energy[b,t,i,j] = sum_d q[b,i,t,d]*k[b,j,t,d]; softmax over j (heads); then
// out[b,i,t,d] = sum_j att * v[b,j,t,d]; written at (r = i*128 + t/16, c = (t%16)*64 + d).
__global__ __launch_bounds__(128) void attn_kernel(
    const float* __restrict__ qkv, float* __restrict__ attn)
{
    __shared__ float sq[3 * EE];     // q|k|v row for this token (12 KB)
    __shared__ float sa[16][17];

    const int m   = blockIdx.x;      // token row: b*2048 + t
    const int b   = m >> 11;
    const int t   = m & 2047;
    const int tid = threadIdx.x;

    const float4* src = reinterpret_cast<const float4*>(qkv + (size_t)m * (3 * EE));
    float4* ds = reinterpret_cast<float4*>(sq);
#pragma unroll
    for (int i = tid; i < 768; i += 128) ds[i] = src[i];
    __syncthreads();

    // 256 energies, 2 per thread
#pragma unroll
    for (int e = tid; e < 256; e += 128) {
        const int i = e >> 4, j = e & 15;
        const float* qi = sq + i * DD;
        const float* kj = sq + EE + j * DD;
        float dot = 0.f;
#pragma unroll
        for (int d = 0; d < DD; ++d) dot += qi[d] * kj[d];
        sa[i][j] = dot * 0.03125f;   // / sqrt(E) = /32
    }
    __syncthreads();

    if (tid < 16) {
        float mx = -1e30f;
#pragma unroll
        for (int j = 0; j < 16; ++j) mx = fmaxf(mx, sa[tid][j]);
        float ex[16], s = 0.f;
#pragma unroll
        for (int j = 0; j < 16; ++j) { ex[j] = expf(sa[tid][j] - mx); s += ex[j]; }
        const float inv = 1.0f / s;
#pragma unroll
        for (int j = 0; j < 16; ++j) sa[tid][j] = ex[j] * inv;
    }
    __syncthreads();

    const int i  = tid >> 3;         // head 0..15
    const int db = (tid & 7) * 8;    // d base
    float o[8] = {0.f, 0.f, 0.f, 0.f, 0.f, 0.f, 0.f, 0.f};
#pragma unroll
    for (int j = 0; j < 16; ++j) {
        const float a = sa[i][j];
        const float* vj = sq + 2 * EE + j * DD + db;
#pragma unroll
        for (int p = 0; p < 8; ++p) o[p] += a * vj[p];
    }
    const int r = i * 128 + (t >> 4);
    const int c = ((t & 15) << 6) + db;
    float* dst = attn + ((size_t)(b * 2048 + r)) * EE + c;
    *reinterpret_cast<float4*>(dst)     = make_float4(o[0], o[1], o[2], o[3]);
    *reinterpret_cast<float4*>(dst + 4) = make_float4(o[4], o[5], o[6], o[7]);
}

// ---------------- row LayerNorm over 1024 cols ----------------
__global__ __launch_bounds__(256) void ln_kernel(
    const float* __restrict__ in, const float* __restrict__ g,
    const float* __restrict__ b, float* __restrict__ out)
{
    __shared__ float red[8];
    __shared__ float s_mean, s_rstd;
    const int row = blockIdx.x;
    const int tid = threadIdx.x;

    const float4 v = reinterpret_cast<const float4*>(in + (size_t)row * EE)[tid];

    float s = v.x + v.y + v.z + v.w;
#pragma unroll
    for (int o = 16; o; o >>= 1) s += __shfl_xor_sync(0xffffffffu, s, o);
    if ((tid & 31) == 0) red[tid >> 5] = s;
    __syncthreads();
    if (tid == 0) {
        float tt = 0.f;
#pragma unroll
        for (int i = 0; i < 8; ++i) tt += red[i];
        s_mean = tt * (1.0f / 1024.0f);
    }
    __syncthreads();
    const float mean = s_mean;

    const float dx = v.x - mean, dy = v.y - mean, dz = v.z - mean, dw = v.w - mean;
    float sq = dx * dx + dy * dy + dz * dz + dw * dw;
#pragma unroll
    for (int o = 16; o; o >>= 1) sq += __shfl_xor_sync(0xffffffffu, sq, o);
    if ((tid & 31) == 0) red[tid >> 5] = sq;
    __syncthreads();
    if (tid == 0) {
        float tt = 0.f;
#pragma unroll
        for (int i = 0; i < 8; ++i) tt += red[i];
        s_rstd = rsqrtf(tt * (1.0f / 1024.0f) + 1e-5f);
    }
    __syncthreads();
    const float rstd = s_rstd;

    const float4 gg = reinterpret_cast<const float4*>(g)[tid];
    const float4 bb = reinterpret_cast<const float4*>(b)[tid];
    float4 o4;
    o4.x = dx * rstd * gg.x + bb.x;
    o4.y = dy * rstd * gg.y + bb.y;
    o4.z = dz * rstd * gg.z + bb.z;
    o4.w = dw * rstd * gg.w + bb.w;
    reinterpret_cast<float4*>(out + (size_t)row * EE)[tid] = o4;
}

// ---------------- launcher ----------------
extern "C" void kernel_launch(void* const* d_in, const int* in_sizes, int n_in,
                              void* d_out, int out_size)
{
    (void)in_sizes; (void)n_in; (void)out_size;
    const float* x     = (const float*)d_in[0];
    const float* Wqkv  = (const float*)d_in[1];
    const float* bqkv  = (const float*)d_in[2];
    const float* Wo    = (const float*)d_in[3];
    const float* bo    = (const float*)d_in[4];
    const float* ln1_g = (const float*)d_in[5];
    const float* ln1_b = (const float*)d_in[6];
    const float* W1    = (const float*)d_in[7];
    const float* bf1   = (const float*)d_in[8];
    const float* W2    = (const float*)d_in[9];
    const float* bf2   = (const float*)d_in[10];
    const float* ln2_g = (const float*)d_in[11];
    const float* ln2_b = (const float*)d_in[12];
    float* out = (float*)d_out;

    void* p;
    cudaGetSymbolAddress(&p, g_qkv);  float* qkv   = (float*)p;
    cudaGetSymbolAddress(&p, g_attn); float* attnb = (float*)p;
    cudaGetSymbolAddress(&p, g_res1); float* res1  = (float*)p;
    cudaGetSymbolAddress(&p, g_h);    float* hbuf  = (float*)p;
    cudaGetSymbolAddress(&p, g_ffn);  float* ffn   = (float*)p;
    cudaGetSymbolAddress(&p, g_res2); float* res2  = (float*)p;

    // 1) QKV projection: (8192,1024) x (3072,1024)^T
    gemm_nt<0><<<dim3(3 * EE / 128, MM / 128), 256>>>(x, Wqkv, bqkv, nullptr, qkv,
                                                      MM, 3 * EE, EE);
    // 2) per-token head attention + scrambled reshape
    attn_kernel<<<MM, 128>>>(qkv, attnb);
    // 3) output projection + residual(x)
    gemm_nt<2><<<dim3(EE / 128, MM / 128), 256>>>(attnb, Wo, bo, x, res1,
                                                  MM, EE, EE);
    // 4) LN1
    ln_kernel<<<MM, 256>>>(res1, ln1_g, ln1_b, hbuf);
    // 5) FFN up + exact GELU
    gemm_nt<1><<<dim3(HID / 128, MM / 128), 256>>>(hbuf, W1, bf1, nullptr, ffn,
                                                   MM, HID, EE);
    // 6) FFN down + residual(h)
    gemm_nt<2><<<dim3(EE / 128, MM / 128), 256>>>(ffn, W2, bf2, hbuf, res2,
                                                  MM, EE, HID);
    // 7) LN2 -> output
    ln_kernel<<<MM, 256>>>(res2, ln2_g, ln2_b, out);
}

// round 3
// speedup vs baseline: 3.0511x; 3.0511x over previous
#include <cuda_runtime.h>
#include <cuda_bf16.h>
#include <math.h>
#include <stdint.h>

// ---------------- problem constants ----------------
#define EE   1024
#define HID  4096
#define MM   8192            // B*N rows

// ---------------- scratch (device globals; no allocation) ----------------
__device__ __align__(128) __nv_bfloat16 g_xh [(size_t)MM * EE];
__device__ __align__(128) __nv_bfloat16 g_xl [(size_t)MM * EE];
__device__ __align__(128) __nv_bfloat16 g_wqh[(size_t)3 * EE * EE];
__device__ __align__(128) __nv_bfloat16 g_wql[(size_t)3 * EE * EE];
__device__ __align__(128) __nv_bfloat16 g_woh[(size_t)EE * EE];
__device__ __align__(128) __nv_bfloat16 g_wol[(size_t)EE * EE];
__device__ __align__(128) __nv_bfloat16 g_w1h[(size_t)HID * EE];
__device__ __align__(128) __nv_bfloat16 g_w1l[(size_t)HID * EE];
__device__ __align__(128) __nv_bfloat16 g_w2h[(size_t)EE * HID];
__device__ __align__(128) __nv_bfloat16 g_w2l[(size_t)EE * HID];
__device__ __align__(128) float         g_qkv[(size_t)MM * 3 * EE];
__device__ __align__(128) __nv_bfloat16 g_ah [(size_t)MM * EE];
__device__ __align__(128) __nv_bfloat16 g_al [(size_t)MM * EE];
__device__ __align__(128) float         g_res1[(size_t)MM * EE];
__device__ __align__(128) float         g_hf  [(size_t)MM * EE];
__device__ __align__(128) __nv_bfloat16 g_hh [(size_t)MM * EE];
__device__ __align__(128) __nv_bfloat16 g_hl [(size_t)MM * EE];
__device__ __align__(128) __nv_bfloat16 g_fh [(size_t)MM * HID];
__device__ __align__(128) __nv_bfloat16 g_fl [(size_t)MM * HID];
__device__ __align__(128) float         g_res2[(size_t)MM * EE];

// ---------------- helpers ----------------
__device__ __forceinline__ void split2(float v, __nv_bfloat16& h, __nv_bfloat16& l) {
    h = __float2bfloat16(v);
    l = __float2bfloat16(v - __bfloat162float(h));
}
__device__ __forceinline__ void ldsm4(uint32_t& r0, uint32_t& r1, uint32_t& r2, uint32_t& r3,
                                      uint32_t a) {
    asm volatile("ldmatrix.sync.aligned.m8n8.x4.shared.b16 {%0,%1,%2,%3}, [%4];"
                 : "=r"(r0), "=r"(r1), "=r"(r2), "=r"(r3) : "r"(a));
}
__device__ __forceinline__ void mma16816(float* c, const uint32_t* a, const uint32_t* b) {
    asm volatile(
        "mma.sync.aligned.m16n8k16.row.col.f32.bf16.bf16.f32 "
        "{%0,%1,%2,%3}, {%4,%5,%6,%7}, {%8,%9}, {%0,%1,%2,%3};"
        : "+f"(c[0]), "+f"(c[1]), "+f"(c[2]), "+f"(c[3])
        : "r"(a[0]), "r"(a[1]), "r"(a[2]), "r"(a[3]), "r"(b[0]), "r"(b[1]));
}
__device__ __forceinline__ void cp16(uint32_t dst, const void* src) {
    asm volatile("cp.async.cg.shared.global [%0], [%1], 16;" :: "r"(dst), "l"(src));
}
__device__ __forceinline__ void cp_commit() { asm volatile("cp.async.commit_group;"); }
template <int N>
__device__ __forceinline__ void cp_wait() { asm volatile("cp.async.wait_group %0;" :: "n"(N)); }

// swizzled 16B-chunk offset within one [128 x 64bf16] smem tile
__device__ __forceinline__ uint32_t swoff(uint32_t r, uint32_t c) {
    return ((r << 3) + (c ^ (r & 7))) << 4;
}

// ---------------- plain hi/lo split ----------------
__global__ __launch_bounds__(256) void split_plain(
    const float* __restrict__ src, __nv_bfloat16* __restrict__ hi,
    __nv_bfloat16* __restrict__ lo, size_t total8)
{
    size_t idx = (size_t)blockIdx.x * blockDim.x + threadIdx.x;
    if (idx >= total8) return;
    const float4 v0 = reinterpret_cast<const float4*>(src)[idx * 2];
    const float4 v1 = reinterpret_cast<const float4*>(src)[idx * 2 + 1];
    float vv[8] = {v0.x, v0.y, v0.z, v0.w, v1.x, v1.y, v1.z, v1.w};
    __align__(16) __nv_bfloat16 hh[8], ll[8];
#pragma unroll
    for (int j = 0; j < 8; ++j) split2(vv[j], hh[j], ll[j]);
    reinterpret_cast<uint4*>(hi)[idx] = *reinterpret_cast<uint4*>(hh);
    reinterpret_cast<uint4*>(lo)[idx] = *reinterpret_cast<uint4*>(ll);
}

// ---------------- bf16-split tensor-core GEMM: C[M,N] = A[M,K] * B[N,K]^T ----------------
// EPI 0: +bias -> Cf ; EPI 1: +bias,GELU -> Chi/Clo ; EPI 2: +bias+res -> Cf
#define STAGES 3
#define STG_BYTES 65536   // Ah 16K | Al 16K | Bh 16K | Bl 16K
#define SMEM_GEMM (STAGES * STG_BYTES)

template <int EPI>
__global__ __launch_bounds__(256, 1) void gemm_mma(
    const __nv_bfloat16* __restrict__ Ahi, const __nv_bfloat16* __restrict__ Alo,
    const __nv_bfloat16* __restrict__ Bhi, const __nv_bfloat16* __restrict__ Blo,
    const float* __restrict__ bias, const float* __restrict__ res,
    float* __restrict__ Cf, __nv_bfloat16* __restrict__ Chi, __nv_bfloat16* __restrict__ Clo,
    int M, int N, int K)
{
    extern __shared__ __align__(128) char smem[];
    const uint32_t sb = (uint32_t)__cvta_generic_to_shared(smem);

    const int tid  = threadIdx.x;
    const int lane = tid & 31;
    const int wid  = tid >> 5;
    const int wm   = wid & 1;        // 2 warps along M (64 each)
    const int wn   = wid >> 1;       // 4 warps along N (32 each)
    const int mblk = blockIdx.y * 128;
    const int nblk = blockIdx.x * 128;

    float acc[4][4][4];
#pragma unroll
    for (int i = 0; i < 4; ++i)
#pragma unroll
        for (int j = 0; j < 4; ++j)
#pragma unroll
            for (int q = 0; q < 4; ++q) acc[i][j][q] = 0.f;

    const int T = K >> 6;   // 64-deep K chunks

    auto load_stage = [&](int s, int kc) {
        const uint32_t base = sb + s * STG_BYTES;
        const int k0 = kc * 64;
#pragma unroll
        for (int i = 0; i < 4; ++i) {
            const int id  = tid + i * 256;           // 0..1023
            const int row = id >> 3;
            const int c   = id & 7;
            const uint32_t so = swoff(row, c);
            const size_t ga = (size_t)(mblk + row) * K + k0 + c * 8;
            const size_t gb = (size_t)(nblk + row) * K + k0 + c * 8;
            cp16(base + so,         Ahi + ga);
            cp16(base + 16384 + so, Alo + ga);
            cp16(base + 32768 + so, Bhi + gb);
            cp16(base + 49152 + so, Blo + gb);
        }
    };

    // prologue: stages 0..STAGES-2
#pragma unroll
    for (int s = 0; s < STAGES - 1; ++s) { load_stage(s, s); cp_commit(); }

    for (int t = 0; t < T; ++t) {
        cp_wait<STAGES - 2>();
        __syncthreads();
        if (t + STAGES - 1 < T) load_stage((t + STAGES - 1) % STAGES, t + STAGES - 1);
        cp_commit();

        const uint32_t stA = sb + (t % STAGES) * STG_BYTES;
        const uint32_t stB = stA + 32768;

#pragma unroll
        for (int ks = 0; ks < 4; ++ks) {
            uint32_t ah[4][4], al[4][4], bh[4][2], bl[4][2];
            // A frags: row-major m16k16 via ldmatrix.x4
            const uint32_t arow = wm * 64 + (lane & 15);
            const uint32_t acol = ks * 2 + (lane >> 4);
#pragma unroll
            for (int mi = 0; mi < 4; ++mi) {
                const uint32_t off = swoff(arow + mi * 16, acol);
                ldsm4(ah[mi][0], ah[mi][1], ah[mi][2], ah[mi][3], stA + off);
                ldsm4(al[mi][0], al[mi][1], al[mi][2], al[mi][3], stA + 16384 + off);
            }
            // B frags: [N,K] row-major, two n8-tiles per ldmatrix.x4
            const uint32_t brow = wn * 32 + (lane & 7) + ((lane >> 4) << 3);
            const uint32_t bcol = ks * 2 + ((lane >> 3) & 1);
#pragma unroll
            for (int pi = 0; pi < 2; ++pi) {
                const uint32_t off = swoff(brow + pi * 16, bcol);
                ldsm4(bh[2 * pi][0], bh[2 * pi][1], bh[2 * pi + 1][0], bh[2 * pi + 1][1],
                      stB + off);
                ldsm4(bl[2 * pi][0], bl[2 * pi][1], bl[2 * pi + 1][0], bl[2 * pi + 1][1],
                      stB + 16384 + off);
            }
#pragma unroll
            for (int mi = 0; mi < 4; ++mi)
#pragma unroll
                for (int ni = 0; ni < 4; ++ni) {
                    mma16816(acc[mi][ni], ah[mi], bh[ni]);
                    mma16816(acc[mi][ni], al[mi], bh[ni]);
                    mma16816(acc[mi][ni], ah[mi], bl[ni]);
                }
        }
    }
    cp_wait<0>();

    // -------- epilogue --------
#pragma unroll
    for (int mi = 0; mi < 4; ++mi) {
#pragma unroll
        for (int ni = 0; ni < 4; ++ni) {
            const int n = nblk + wn * 32 + ni * 8 + (lane & 3) * 2;
            const float b0 = bias[n], b1 = bias[n + 1];
            const int m0 = mblk + wm * 64 + mi * 16 + (lane >> 2);
#pragma unroll
            for (int half = 0; half < 2; ++half) {
                const int m = m0 + half * 8;
                float v0 = acc[mi][ni][half * 2 + 0] + b0;
                float v1 = acc[mi][ni][half * 2 + 1] + b1;
                if (EPI == 2) {
                    const float2 rv = *reinterpret_cast<const float2*>(res + (size_t)m * N + n);
                    v0 += rv.x; v1 += rv.y;
                }
                if (EPI == 0 || EPI == 2) {
                    *reinterpret_cast<float2*>(Cf + (size_t)m * N + n) = make_float2(v0, v1);
                } else {
                    v0 = 0.5f * v0 * (1.0f + erff(v0 * 0.70710678118654752f));
                    v1 = 0.5f * v1 * (1.0f + erff(v1 * 0.70710678118654752f));
                    __nv_bfloat162 h2, l2;
                    split2(v0, h2.x, l2.x);
                    split2(v1, h2.y, l2.y);
                    *reinterpret_cast<__nv_bfloat162*>(Chi + (size_t)m * N + n) = h2;
                    *reinterpret_cast<__nv_bfloat162*>(Clo + (size_t)m * N + n) = l2;
                }
            }
        }
    }
}

// ---------------- per-token head-softmax attention -> hi/lo plain output ----------------
__global__ __launch_bounds__(128) void attn_kernel(
    const float* __restrict__ qkv, __nv_bfloat16* __restrict__ ahi,
    __nv_bfloat16* __restrict__ alo)
{
    __shared__ float sq[3 * EE];
    __shared__ float sa[16][17];

    const int mrow = blockIdx.x;     // b*2048 + t
    const int b    = mrow >> 11;
    const int t    = mrow & 2047;
    const int tid  = threadIdx.x;

    const float4* src = reinterpret_cast<const float4*>(qkv + (size_t)mrow * (3 * EE));
    float4* ds = reinterpret_cast<float4*>(sq);
#pragma unroll
    for (int i = tid; i < 768; i += 128) ds[i] = src[i];
    __syncthreads();

#pragma unroll
    for (int e = tid; e < 256; e += 128) {
        const int i = e >> 4, j = e & 15;
        const float* qi = sq + i * 64;
        const float* kj = sq + EE + j * 64;
        float dot = 0.f;
#pragma unroll
        for (int d = 0; d < 64; ++d) dot += qi[d] * kj[d];
        sa[i][j] = dot * 0.03125f;   // / sqrt(E)=32
    }
    __syncthreads();

    if (tid < 16) {
        float mx = -1e30f;
#pragma unroll
        for (int j = 0; j < 16; ++j) mx = fmaxf(mx, sa[tid][j]);
        float ex[16], s = 0.f;
#pragma unroll
        for (int j = 0; j < 16; ++j) { ex[j] = expf(sa[tid][j] - mx); s += ex[j]; }
        const float inv = 1.0f / s;
#pragma unroll
        for (int j = 0; j < 16; ++j) sa[tid][j] = ex[j] * inv;
    }
    __syncthreads();

    const int i  = tid >> 3;
    const int db = (tid & 7) * 8;
    float o[8] = {0.f, 0.f, 0.f, 0.f, 0.f, 0.f, 0.f, 0.f};
#pragma unroll
    for (int j = 0; j < 16; ++j) {
        const float a = sa[i][j];
        const float* vj = sq + 2 * EE + j * 64 + db;
#pragma unroll
        for (int p = 0; p < 8; ++p) o[p] += a * vj[p];
    }
    // scrambled target: row = i*128 + t/16, col = (t%16)*64 + db
    const int m = b * 2048 + i * 128 + (t >> 4);
    const int c = ((t & 15) << 6) + db;
    __align__(16) __nv_bfloat16 hh[8], ll[8];
#pragma unroll
    for (int p = 0; p < 8; ++p) split2(o[p], hh[p], ll[p]);
    *reinterpret_cast<uint4*>(ahi + (size_t)m * EE + c) = *reinterpret_cast<uint4*>(hh);
    *reinterpret_cast<uint4*>(alo + (size_t)m * EE + c) = *reinterpret_cast<uint4*>(ll);
}

// ---------------- row LayerNorm (optionally also emits hi/lo bf16) ----------------
template <bool SPLIT>
__global__ __launch_bounds__(256) void ln_kernel(
    const float* __restrict__ in, const float* __restrict__ g, const float* __restrict__ b,
    float* __restrict__ outf, __nv_bfloat16* __restrict__ ohi, __nv_bfloat16* __restrict__ olo)
{
    __shared__ float red[8];
    __shared__ float s_mean, s_rstd;
    const int row = blockIdx.x;
    const int tid = threadIdx.x;

    const float4 v = reinterpret_cast<const float4*>(in + (size_t)row * EE)[tid];

    float s = v.x + v.y + v.z + v.w;
#pragma unroll
    for (int o = 16; o; o >>= 1) s += __shfl_xor_sync(0xffffffffu, s, o);
    if ((tid & 31) == 0) red[tid >> 5] = s;
    __syncthreads();
    if (tid == 0) {
        float tt = 0.f;
#pragma unroll
        for (int i = 0; i < 8; ++i) tt += red[i];
        s_mean = tt * (1.0f / 1024.0f);
    }
    __syncthreads();
    const float mean = s_mean;

    const float dx = v.x - mean, dy = v.y - mean, dz = v.z - mean, dw = v.w - mean;
    float sq = dx * dx + dy * dy + dz * dz + dw * dw;
#pragma unroll
    for (int o = 16; o; o >>= 1) sq += __shfl_xor_sync(0xffffffffu, sq, o);
    if ((tid & 31) == 0) red[tid >> 5] = sq;
    __syncthreads();
    if (tid == 0) {
        float tt = 0.f;
#pragma unroll
        for (int i = 0; i < 8; ++i) tt += red[i];
        s_rstd = rsqrtf(tt * (1.0f / 1024.0f) + 1e-5f);
    }
    __syncthreads();
    const float rstd = s_rstd;

    const float4 gg = reinterpret_cast<const float4*>(g)[tid];
    const float4 bb = reinterpret_cast<const float4*>(b)[tid];
    float4 o4;
    o4.x = dx * rstd * gg.x + bb.x;
    o4.y = dy * rstd * gg.y + bb.y;
    o4.z = dz * rstd * gg.z + bb.z;
    o4.w = dw * rstd * gg.w + bb.w;
    reinterpret_cast<float4*>(outf + (size_t)row * EE)[tid] = o4;

    if (SPLIT) {
        __align__(8) __nv_bfloat16 hh[4], ll[4];
        split2(o4.x, hh[0], ll[0]); split2(o4.y, hh[1], ll[1]);
        split2(o4.z, hh[2], ll[2]); split2(o4.w, hh[3], ll[3]);
        const size_t base = (size_t)row * EE + tid * 4;
        *reinterpret_cast<uint2*>(ohi + base) = *reinterpret_cast<uint2*>(hh);
        *reinterpret_cast<uint2*>(olo + base) = *reinterpret_cast<uint2*>(ll);
    }
}

// ---------------- launcher ----------------
extern "C" void kernel_launch(void* const* d_in, const int* in_sizes, int n_in,
                              void* d_out, int out_size)
{
    (void)in_sizes; (void)n_in; (void)out_size;
    const float* x     = (const float*)d_in[0];
    const float* Wqkv  = (const float*)d_in[1];
    const float* bqkv  = (const float*)d_in[2];
    const float* Wo    = (const float*)d_in[3];
    const float* bo    = (const float*)d_in[4];
    const float* ln1_g = (const float*)d_in[5];
    const float* ln1_b = (const float*)d_in[6];
    const float* W1    = (const float*)d_in[7];
    const float* bf1   = (const float*)d_in[8];
    const float* W2    = (const float*)d_in[9];
    const float* bf2   = (const float*)d_in[10];
    const float* ln2_g = (const float*)d_in[11];
    const float* ln2_b = (const float*)d_in[12];
    float* out = (float*)d_out;

    static bool attr_done = false;
    if (!attr_done) {
        cudaFuncSetAttribute(gemm_mma<0>, cudaFuncAttributeMaxDynamicSharedMemorySize, SMEM_GEMM);
        cudaFuncSetAttribute(gemm_mma<1>, cudaFuncAttributeMaxDynamicSharedMemorySize, SMEM_GEMM);
        cudaFuncSetAttribute(gemm_mma<2>, cudaFuncAttributeMaxDynamicSharedMemorySize, SMEM_GEMM);
        attr_done = true;
    }

    void* p;
    cudaGetSymbolAddress(&p, g_xh);   __nv_bfloat16* xh  = (__nv_bfloat16*)p;
    cudaGetSymbolAddress(&p, g_xl);   __nv_bfloat16* xl  = (__nv_bfloat16*)p;
    cudaGetSymbolAddress(&p, g_wqh);  __nv_bfloat16* wqh = (__nv_bfloat16*)p;
    cudaGetSymbolAddress(&p, g_wql);  __nv_bfloat16* wql = (__nv_bfloat16*)p;
    cudaGetSymbolAddress(&p, g_woh);  __nv_bfloat16* woh = (__nv_bfloat16*)p;
    cudaGetSymbolAddress(&p, g_wol);  __nv_bfloat16* wol = (__nv_bfloat16*)p;
    cudaGetSymbolAddress(&p, g_w1h);  __nv_bfloat16* w1h = (__nv_bfloat16*)p;
    cudaGetSymbolAddress(&p, g_w1l);  __nv_bfloat16* w1l = (__nv_bfloat16*)p;
    cudaGetSymbolAddress(&p, g_w2h);  __nv_bfloat16* w2h = (__nv_bfloat16*)p;
    cudaGetSymbolAddress(&p, g_w2l);  __nv_bfloat16* w2l = (__nv_bfloat16*)p;
    cudaGetSymbolAddress(&p, g_qkv);  float* qkv  = (float*)p;
    cudaGetSymbolAddress(&p, g_ah);   __nv_bfloat16* ah = (__nv_bfloat16*)p;
    cudaGetSymbolAddress(&p, g_al);   __nv_bfloat16* al = (__nv_bfloat16*)p;
    cudaGetSymbolAddress(&p, g_res1); float* res1 = (float*)p;
    cudaGetSymbolAddress(&p, g_hf);   float* hf   = (float*)p;
    cudaGetSymbolAddress(&p, g_hh);   __nv_bfloat16* hh = (__nv_bfloat16*)p;
    cudaGetSymbolAddress(&p, g_hl);   __nv_bfloat16* hl = (__nv_bfloat16*)p;
    cudaGetSymbolAddress(&p, g_fh);   __nv_bfloat16* fh = (__nv_bfloat16*)p;
    cudaGetSymbolAddress(&p, g_fl);   __nv_bfloat16* fl = (__nv_bfloat16*)p;
    cudaGetSymbolAddress(&p, g_res2); float* res2 = (float*)p;

    // operand hi/lo splits
    split_plain<<<(MM * EE / 8 + 255) / 256, 256>>>(x, xh, xl, (size_t)MM * EE / 8);
    split_plain<<<(3 * EE * EE / 8 + 255) / 256, 256>>>(Wqkv, wqh, wql, (size_t)3 * EE * EE / 8);
    split_plain<<<(EE * EE / 8 + 255) / 256, 256>>>(Wo, woh, wol, (size_t)EE * EE / 8);
    split_plain<<<(HID * EE / 8 + 255) / 256, 256>>>(W1, w1h, w1l, (size_t)HID * EE / 8);
    split_plain<<<(EE * HID / 8 + 255) / 256, 256>>>(W2, w2h, w2l, (size_t)EE * HID / 8);

    // 1) QKV projection
    gemm_mma<0><<<dim3(24, 64), 256, SMEM_GEMM>>>(xh, xl, wqh, wql, bqkv, nullptr,
                                                  qkv, nullptr, nullptr, MM, 3 * EE, EE);
    // 2) head-softmax attention + scrambled reshape
    attn_kernel<<<MM, 128>>>(qkv, ah, al);
    // 3) output projection + residual(x)
    gemm_mma<2><<<dim3(8, 64), 256, SMEM_GEMM>>>(ah, al, woh, wol, bo, x,
                                                 res1, nullptr, nullptr, MM, EE, EE);
    // 4) LN1 -> h (fp32 + hi/lo)
    ln_kernel<true><<<MM, 256>>>(res1, ln1_g, ln1_b, hf, hh, hl);
    // 5) FFN up + GELU -> hi/lo
    gemm_mma<1><<<dim3(32, 64), 256, SMEM_GEMM>>>(hh, hl, w1h, w1l, bf1, nullptr,
                                                  nullptr, fh, fl, MM, HID, EE);
    // 6) FFN down + residual(h)
    gemm_mma<2><<<dim3(8, 64), 256, SMEM_GEMM>>>(fh, fl, w2h, w2l, bf2, hf,
                                                 res2, nullptr, nullptr, MM, EE, HID);
    // 7) LN2 -> output
    ln_kernel<false><<<MM, 256>>>(res2, ln2_g, ln2_b, out, nullptr, nullptr);
}

// round 4
// speedup vs baseline: 3.1559x; 1.0343x over previous
#include <cuda_runtime.h>
#include <cuda_bf16.h>
#include <math.h>
#include <stdint.h>

// ---------------- problem constants ----------------
#define EE   1024
#define HID  4096
#define MM   8192            // B*N rows

// ---------------- scratch (device globals; no allocation) ----------------
__device__ __align__(128) __nv_bfloat16 g_xh [(size_t)MM * EE];
__device__ __align__(128) __nv_bfloat16 g_xl [(size_t)MM * EE];
__device__ __align__(128) __nv_bfloat16 g_wqh[(size_t)3 * EE * EE];
__device__ __align__(128) __nv_bfloat16 g_wql[(size_t)3 * EE * EE];
__device__ __align__(128) __nv_bfloat16 g_woh[(size_t)EE * EE];
__device__ __align__(128) __nv_bfloat16 g_wol[(size_t)EE * EE];
__device__ __align__(128) __nv_bfloat16 g_w1h[(size_t)HID * EE];
__device__ __align__(128) __nv_bfloat16 g_w1l[(size_t)HID * EE];
__device__ __align__(128) __nv_bfloat16 g_w2h[(size_t)EE * HID];
__device__ __align__(128) __nv_bfloat16 g_w2l[(size_t)EE * HID];
__device__ __align__(128) float         g_qkv[(size_t)MM * 3 * EE];
__device__ __align__(128) __nv_bfloat16 g_ah [(size_t)MM * EE];
__device__ __align__(128) __nv_bfloat16 g_al [(size_t)MM * EE];
__device__ __align__(128) float         g_res1[(size_t)MM * EE];
__device__ __align__(128) float         g_hf  [(size_t)MM * EE];
__device__ __align__(128) __nv_bfloat16 g_hh [(size_t)MM * EE];
__device__ __align__(128) __nv_bfloat16 g_hl [(size_t)MM * EE];
__device__ __align__(128) __nv_bfloat16 g_fh [(size_t)MM * HID];
__device__ __align__(128) __nv_bfloat16 g_fl [(size_t)MM * HID];
__device__ __align__(128) float         g_res2[(size_t)MM * EE];

// ---------------- helpers ----------------
__device__ __forceinline__ void split2(float v, __nv_bfloat16& h, __nv_bfloat16& l) {
    h = __float2bfloat16(v);
    l = __float2bfloat16(v - __bfloat162float(h));
}
__device__ __forceinline__ void ldsm4(uint32_t& r0, uint32_t& r1, uint32_t& r2, uint32_t& r3,
                                      uint32_t a) {
    asm volatile("ldmatrix.sync.aligned.m8n8.x4.shared.b16 {%0,%1,%2,%3}, [%4];"
                 : "=r"(r0), "=r"(r1), "=r"(r2), "=r"(r3) : "r"(a));
}
__device__ __forceinline__ void mma16816(float* c, const uint32_t* a, const uint32_t* b) {
    asm volatile(
        "mma.sync.aligned.m16n8k16.row.col.f32.bf16.bf16.f32 "
        "{%0,%1,%2,%3}, {%4,%5,%6,%7}, {%8,%9}, {%0,%1,%2,%3};"
        : "+f"(c[0]), "+f"(c[1]), "+f"(c[2]), "+f"(c[3])
        : "r"(a[0]), "r"(a[1]), "r"(a[2]), "r"(a[3]), "r"(b[0]), "r"(b[1]));
}
__device__ __forceinline__ void cp16(uint32_t dst, const void* src) {
    asm volatile("cp.async.cg.shared.global [%0], [%1], 16;" :: "r"(dst), "l"(src));
}
__device__ __forceinline__ void cp_commit() { asm volatile("cp.async.commit_group;"); }
template <int N>
__device__ __forceinline__ void cp_wait() { asm volatile("cp.async.wait_group %0;" :: "n"(N)); }

// swizzled 16B-chunk offset within [rows x 64bf16] smem region (row-major 128B rows)
__device__ __forceinline__ uint32_t swoff(uint32_t r, uint32_t c) {
    return ((r << 3) + (c ^ (r & 7))) << 4;
}

// ---------------- plain hi/lo split ----------------
__global__ __launch_bounds__(256) void split_plain(
    const float* __restrict__ src, __nv_bfloat16* __restrict__ hi,
    __nv_bfloat16* __restrict__ lo, size_t total8)
{
    size_t idx = (size_t)blockIdx.x * blockDim.x + threadIdx.x;
    if (idx >= total8) return;
    const float4 v0 = reinterpret_cast<const float4*>(src)[idx * 2];
    const float4 v1 = reinterpret_cast<const float4*>(src)[idx * 2 + 1];
    float vv[8] = {v0.x, v0.y, v0.z, v0.w, v1.x, v1.y, v1.z, v1.w};
    __align__(16) __nv_bfloat16 hh[8], ll[8];
#pragma unroll
    for (int j = 0; j < 8; ++j) split2(vv[j], hh[j], ll[j]);
    reinterpret_cast<uint4*>(hi)[idx] = *reinterpret_cast<uint4*>(hh);
    reinterpret_cast<uint4*>(lo)[idx] = *reinterpret_cast<uint4*>(ll);
}

// ---------------- bf16-split tensor-core GEMM: C[M,N] = A[M,K] * B[N,K]^T ----------------
// Tile: 256x128, BK=64, 2 stages. 8 warps as 4(M) x 2(N), each 64x64.
// Stage layout: [Ah 32K][Al 32K][Bh 16K][Bl 16K] = 96KB
// EPI 0: +bias -> Cf ; EPI 1: +bias,GELU -> Chi/Clo ; EPI 2: +bias+res -> Cf
#define STG_BYTES 98304
#define SMEM_GEMM (2 * STG_BYTES)

template <int EPI>
__global__ __launch_bounds__(256, 1) void gemm_mma(
    const __nv_bfloat16* __restrict__ Ahi, const __nv_bfloat16* __restrict__ Alo,
    const __nv_bfloat16* __restrict__ Bhi, const __nv_bfloat16* __restrict__ Blo,
    const float* __restrict__ bias, const float* __restrict__ res,
    float* __restrict__ Cf, __nv_bfloat16* __restrict__ Chi, __nv_bfloat16* __restrict__ Clo,
    int M, int N, int K)
{
    extern __shared__ __align__(128) char smem[];
    const uint32_t sb = (uint32_t)__cvta_generic_to_shared(smem);

    const int tid  = threadIdx.x;
    const int lane = tid & 31;
    const int wid  = tid >> 5;
    const int wm   = wid & 3;        // 4 warps along M (64 rows each)
    const int wn   = wid >> 2;       // 2 warps along N (64 cols each)
    const int mblk = blockIdx.y * 256;
    const int nblk = blockIdx.x * 128;

    float acc[4][8][4];
#pragma unroll
    for (int i = 0; i < 4; ++i)
#pragma unroll
        for (int j = 0; j < 8; ++j)
#pragma unroll
            for (int q = 0; q < 4; ++q) acc[i][j][q] = 0.f;

    const int T = K >> 6;

    auto load_stage = [&](int s, int kc) {
        const uint32_t base = sb + s * STG_BYTES;
        const int k0 = kc * 64;
#pragma unroll
        for (int i = 0; i < 8; ++i) {               // A: 256 rows
            const int id  = tid + i * 256;
            const int row = id >> 3;
            const int c   = id & 7;
            const uint32_t so = swoff(row, c);
            const size_t ga = (size_t)(mblk + row) * K + k0 + c * 8;
            cp16(base + so,         Ahi + ga);
            cp16(base + 32768 + so, Alo + ga);
        }
#pragma unroll
        for (int i = 0; i < 4; ++i) {               // B: 128 rows
            const int id  = tid + i * 256;
            const int row = id >> 3;
            const int c   = id & 7;
            const uint32_t so = swoff(row, c);
            const size_t gb = (size_t)(nblk + row) * K + k0 + c * 8;
            cp16(base + 65536 + so, Bhi + gb);
            cp16(base + 81920 + so, Blo + gb);
        }
    };

    load_stage(0, 0);
    cp_commit();

    for (int t = 0; t < T; ++t) {
        if (t + 1 < T) load_stage((t + 1) & 1, t + 1);
        cp_commit();
        cp_wait<1>();
        __syncthreads();

        const uint32_t stA = sb + (t & 1) * STG_BYTES;
        const uint32_t stB = stA + 65536;

#pragma unroll
        for (int ks = 0; ks < 4; ++ks) {
            uint32_t ah[4][4], al[4][4], b[8][2];
            const uint32_t arow = wm * 64 + (lane & 15);
            const uint32_t acol = ks * 2 + (lane >> 4);
#pragma unroll
            for (int mi = 0; mi < 4; ++mi) {
                const uint32_t off = swoff(arow + mi * 16, acol);
                ldsm4(ah[mi][0], ah[mi][1], ah[mi][2], ah[mi][3], stA + off);
                ldsm4(al[mi][0], al[mi][1], al[mi][2], al[mi][3], stA + 32768 + off);
            }
            const uint32_t brow = wn * 64 + (lane & 7) + ((lane >> 4) << 3);
            const uint32_t bcol = ks * 2 + ((lane >> 3) & 1);
#pragma unroll
            for (int pi = 0; pi < 4; ++pi) {
                const uint32_t off = swoff(brow + pi * 16, bcol);
                ldsm4(b[2 * pi][0], b[2 * pi][1], b[2 * pi + 1][0], b[2 * pi + 1][1],
                      stB + off);
            }
#pragma unroll
            for (int mi = 0; mi < 4; ++mi)
#pragma unroll
                for (int ni = 0; ni < 8; ++ni) mma16816(acc[mi][ni], ah[mi], b[ni]);
#pragma unroll
            for (int mi = 0; mi < 4; ++mi)
#pragma unroll
                for (int ni = 0; ni < 8; ++ni) mma16816(acc[mi][ni], al[mi], b[ni]);
            // reuse b regs for B_lo
#pragma unroll
            for (int pi = 0; pi < 4; ++pi) {
                const uint32_t off = swoff(brow + pi * 16, bcol);
                ldsm4(b[2 * pi][0], b[2 * pi][1], b[2 * pi + 1][0], b[2 * pi + 1][1],
                      stB + 16384 + off);
            }
#pragma unroll
            for (int mi = 0; mi < 4; ++mi)
#pragma unroll
                for (int ni = 0; ni < 8; ++ni) mma16816(acc[mi][ni], ah[mi], b[ni]);
        }
        __syncthreads();
    }
    cp_wait<0>();

    // -------- epilogue --------
#pragma unroll
    for (int mi = 0; mi < 4; ++mi) {
#pragma unroll
        for (int ni = 0; ni < 8; ++ni) {
            const int n = nblk + wn * 64 + ni * 8 + (lane & 3) * 2;
            const float b0 = bias[n], b1 = bias[n + 1];
            const int m0 = mblk + wm * 64 + mi * 16 + (lane >> 2);
#pragma unroll
            for (int half = 0; half < 2; ++half) {
                const int m = m0 + half * 8;
                float v0 = acc[mi][ni][half * 2 + 0] + b0;
                float v1 = acc[mi][ni][half * 2 + 1] + b1;
                if (EPI == 2) {
                    const float2 rv = *reinterpret_cast<const float2*>(res + (size_t)m * N + n);
                    v0 += rv.x; v1 += rv.y;
                }
                if (EPI == 0 || EPI == 2) {
                    *reinterpret_cast<float2*>(Cf + (size_t)m * N + n) = make_float2(v0, v1);
                } else {
                    v0 = 0.5f * v0 * (1.0f + erff(v0 * 0.70710678118654752f));
                    v1 = 0.5f * v1 * (1.0f + erff(v1 * 0.70710678118654752f));
                    __nv_bfloat162 h2, l2;
                    split2(v0, h2.x, l2.x);
                    split2(v1, h2.y, l2.y);
                    *reinterpret_cast<__nv_bfloat162*>(Chi + (size_t)m * N + n) = h2;
                    *reinterpret_cast<__nv_bfloat162*>(Clo + (size_t)m * N + n) = l2;
                }
            }
        }
    }
}

// ---------------- per-token head-softmax attention -> hi/lo plain output ----------------
__global__ __launch_bounds__(128) void attn_kernel(
    const float* __restrict__ qkv, __nv_bfloat16* __restrict__ ahi,
    __nv_bfloat16* __restrict__ alo)
{
    __shared__ float sq[3 * EE];
    __shared__ float sa[16][17];

    const int mrow = blockIdx.x;     // b*2048 + t
    const int b    = mrow >> 11;
    const int t    = mrow & 2047;
    const int tid  = threadIdx.x;

    const float4* src = reinterpret_cast<const float4*>(qkv + (size_t)mrow * (3 * EE));
    float4* ds = reinterpret_cast<float4*>(sq);
#pragma unroll
    for (int i = tid; i < 768; i += 128) ds[i] = src[i];
    __syncthreads();

#pragma unroll
    for (int e = tid; e < 256; e += 128) {
        const int i = e >> 4, j = e & 15;
        const float* qi = sq + i * 64;
        const float* kj = sq + EE + j * 64;
        float dot = 0.f;
#pragma unroll
        for (int d = 0; d < 64; ++d) dot += qi[d] * kj[d];
        sa[i][j] = dot * 0.03125f;   // / sqrt(E)=32
    }
    __syncthreads();

    if (tid < 16) {
        float mx = -1e30f;
#pragma unroll
        for (int j = 0; j < 16; ++j) mx = fmaxf(mx, sa[tid][j]);
        float ex[16], s = 0.f;
#pragma unroll
        for (int j = 0; j < 16; ++j) { ex[j] = expf(sa[tid][j] - mx); s += ex[j]; }
        const float inv = 1.0f / s;
#pragma unroll
        for (int j = 0; j < 16; ++j) sa[tid][j] = ex[j] * inv;
    }
    __syncthreads();

    const int i  = tid >> 3;
    const int db = (tid & 7) * 8;
    float o[8] = {0.f, 0.f, 0.f, 0.f, 0.f, 0.f, 0.f, 0.f};
#pragma unroll
    for (int j = 0; j < 16; ++j) {
        const float a = sa[i][j];
        const float* vj = sq + 2 * EE + j * 64 + db;
#pragma unroll
        for (int p = 0; p < 8; ++p) o[p] += a * vj[p];
    }
    // scrambled target: row = i*128 + t/16, col = (t%16)*64 + db
    const int m = b * 2048 + i * 128 + (t >> 4);
    const int c = ((t & 15) << 6) + db;
    __align__(16) __nv_bfloat16 hh[8], ll[8];
#pragma unroll
    for (int p = 0; p < 8; ++p) split2(o[p], hh[p], ll[p]);
    *reinterpret_cast<uint4*>(ahi + (size_t)m * EE + c) = *reinterpret_cast<uint4*>(hh);
    *reinterpret_cast<uint4*>(alo + (size_t)m * EE + c) = *reinterpret_cast<uint4*>(ll);
}

// ---------------- row LayerNorm (optionally also emits hi/lo bf16) ----------------
template <bool SPLIT>
__global__ __launch_bounds__(256) void ln_kernel(
    const float* __restrict__ in, const float* __restrict__ g, const float* __restrict__ b,
    float* __restrict__ outf, __nv_bfloat16* __restrict__ ohi, __nv_bfloat16* __restrict__ olo)
{
    __shared__ float red[8];
    __shared__ float s_mean, s_rstd;
    const int row = blockIdx.x;
    const int tid = threadIdx.x;

    const float4 v = reinterpret_cast<const float4*>(in + (size_t)row * EE)[tid];

    float s = v.x + v.y + v.z + v.w;
#pragma unroll
    for (int o = 16; o; o >>= 1) s += __shfl_xor_sync(0xffffffffu, s, o);
    if ((tid & 31) == 0) red[tid >> 5] = s;
    __syncthreads();
    if (tid == 0) {
        float tt = 0.f;
#pragma unroll
        for (int i = 0; i < 8; ++i) tt += red[i];
        s_mean = tt * (1.0f / 1024.0f);
    }
    __syncthreads();
    const float mean = s_mean;

    const float dx = v.x - mean, dy = v.y - mean, dz = v.z - mean, dw = v.w - mean;
    float sq = dx * dx + dy * dy + dz * dz + dw * dw;
#pragma unroll
    for (int o = 16; o; o >>= 1) sq += __shfl_xor_sync(0xffffffffu, sq, o);
    if ((tid & 31) == 0) red[tid >> 5] = sq;
    __syncthreads();
    if (tid == 0) {
        float tt = 0.f;
#pragma unroll
        for (int i = 0; i < 8; ++i) tt += red[i];
        s_rstd = rsqrtf(tt * (1.0f / 1024.0f) + 1e-5f);
    }
    __syncthreads();
    const float rstd = s_rstd;

    const float4 gg = reinterpret_cast<const float4*>(g)[tid];
    const float4 bb = reinterpret_cast<const float4*>(b)[tid];
    float4 o4;
    o4.x = dx * rstd * gg.x + bb.x;
    o4.y = dy * rstd * gg.y + bb.y;
    o4.z = dz * rstd * gg.z + bb.z;
    o4.w = dw * rstd * gg.w + bb.w;
    reinterpret_cast<float4*>(outf + (size_t)row * EE)[tid] = o4;

    if (SPLIT) {
        __align__(8) __nv_bfloat16 hh[4], ll[4];
        split2(o4.x, hh[0], ll[0]); split2(o4.y, hh[1], ll[1]);
        split2(o4.z, hh[2], ll[2]); split2(o4.w, hh[3], ll[3]);
        const size_t base = (size_t)row * EE + tid * 4;
        *reinterpret_cast<uint2*>(ohi + base) = *reinterpret_cast<uint2*>(hh);
        *reinterpret_cast<uint2*>(olo + base) = *reinterpret_cast<uint2*>(ll);
    }
}

// ---------------- launcher ----------------
extern "C" void kernel_launch(void* const* d_in, const int* in_sizes, int n_in,
                              void* d_out, int out_size)
{
    (void)in_sizes; (void)n_in; (void)out_size;
    const float* x     = (const float*)d_in[0];
    const float* Wqkv  = (const float*)d_in[1];
    const float* bqkv  = (const float*)d_in[2];
    const float* Wo    = (const float*)d_in[3];
    const float* bo    = (const float*)d_in[4];
    const float* ln1_g = (const float*)d_in[5];
    const float* ln1_b = (const float*)d_in[6];
    const float* W1    = (const float*)d_in[7];
    const float* bf1   = (const float*)d_in[8];
    const float* W2    = (const float*)d_in[9];
    const float* bf2   = (const float*)d_in[10];
    const float* ln2_g = (const float*)d_in[11];
    const float* ln2_b = (const float*)d_in[12];
    float* out = (float*)d_out;

    static bool attr_done = false;
    if (!attr_done) {
        cudaFuncSetAttribute(gemm_mma<0>, cudaFuncAttributeMaxDynamicSharedMemorySize, SMEM_GEMM);
        cudaFuncSetAttribute(gemm_mma<1>, cudaFuncAttributeMaxDynamicSharedMemorySize, SMEM_GEMM);
        cudaFuncSetAttribute(gemm_mma<2>, cudaFuncAttributeMaxDynamicSharedMemorySize, SMEM_GEMM);
        attr_done = true;
    }

    void* p;
    cudaGetSymbolAddress(&p, g_xh);   __nv_bfloat16* xh  = (__nv_bfloat16*)p;
    cudaGetSymbolAddress(&p, g_xl);   __nv_bfloat16* xl  = (__nv_bfloat16*)p;
    cudaGetSymbolAddress(&p, g_wqh);  __nv_bfloat16* wqh = (__nv_bfloat16*)p;
    cudaGetSymbolAddress(&p, g_wql);  __nv_bfloat16* wql = (__nv_bfloat16*)p;
    cudaGetSymbolAddress(&p, g_woh);  __nv_bfloat16* woh = (__nv_bfloat16*)p;
    cudaGetSymbolAddress(&p, g_wol);  __nv_bfloat16* wol = (__nv_bfloat16*)p;
    cudaGetSymbolAddress(&p, g_w1h);  __nv_bfloat16* w1h = (__nv_bfloat16*)p;
    cudaGetSymbolAddress(&p, g_w1l);  __nv_bfloat16* w1l = (__nv_bfloat16*)p;
    cudaGetSymbolAddress(&p, g_w2h);  __nv_bfloat16* w2h = (__nv_bfloat16*)p;
    cudaGetSymbolAddress(&p, g_w2l);  __nv_bfloat16* w2l = (__nv_bfloat16*)p;
    cudaGetSymbolAddress(&p, g_qkv);  float* qkv  = (float*)p;
    cudaGetSymbolAddress(&p, g_ah);   __nv_bfloat16* ah = (__nv_bfloat16*)p;
    cudaGetSymbolAddress(&p, g_al);   __nv_bfloat16* al = (__nv_bfloat16*)p;
    cudaGetSymbolAddress(&p, g_res1); float* res1 = (float*)p;
    cudaGetSymbolAddress(&p, g_hf);   float* hf   = (float*)p;
    cudaGetSymbolAddress(&p, g_hh);   __nv_bfloat16* hh = (__nv_bfloat16*)p;
    cudaGetSymbolAddress(&p, g_hl);   __nv_bfloat16* hl = (__nv_bfloat16*)p;
    cudaGetSymbolAddress(&p, g_fh);   __nv_bfloat16* fh = (__nv_bfloat16*)p;
    cudaGetSymbolAddress(&p, g_fl);   __nv_bfloat16* fl = (__nv_bfloat16*)p;
    cudaGetSymbolAddress(&p, g_res2); float* res2 = (float*)p;

    // operand hi/lo splits
    split_plain<<<(MM * EE / 8 + 255) / 256, 256>>>(x, xh, xl, (size_t)MM * EE / 8);
    split_plain<<<(3 * EE * EE / 8 + 255) / 256, 256>>>(Wqkv, wqh, wql, (size_t)3 * EE * EE / 8);
    split_plain<<<(EE * EE / 8 + 255) / 256, 256>>>(Wo, woh, wol, (size_t)EE * EE / 8);
    split_plain<<<(HID * EE / 8 + 255) / 256, 256>>>(W1, w1h, w1l, (size_t)HID * EE / 8);
    split_plain<<<(EE * HID / 8 + 255) / 256, 256>>>(W2, w2h, w2l, (size_t)EE * HID / 8);

    // 1) QKV projection (M=8192 -> 32 M-tiles of 256)
    gemm_mma<0><<<dim3(24, 32), 256, SMEM_GEMM>>>(xh, xl, wqh, wql, bqkv, nullptr,
                                                  qkv, nullptr, nullptr, MM, 3 * EE, EE);
    // 2) head-softmax attention + scrambled reshape
    attn_kernel<<<MM, 128>>>(qkv, ah, al);
    // 3) output projection + residual(x)
    gemm_mma<2><<<dim3(8, 32), 256, SMEM_GEMM>>>(ah, al, woh, wol, bo, x,
                                                 res1, nullptr, nullptr, MM, EE, EE);
    // 4) LN1 -> h (fp32 + hi/lo)
    ln_kernel<true><<<MM, 256>>>(res1, ln1_g, ln1_b, hf, hh, hl);
    // 5) FFN up + GELU -> hi/lo
    gemm_mma<1><<<dim3(32, 32), 256, SMEM_GEMM>>>(hh, hl, w1h, w1l, bf1, nullptr,
                                                  nullptr, fh, fl, MM, HID, EE);
    // 6) FFN down + residual(h)
    gemm_mma<2><<<dim3(8, 32), 256, SMEM_GEMM>>>(fh, fl, w2h, w2l, bf2, hf,
                                                 res2, nullptr, nullptr, MM, EE, HID);
    // 7) LN2 -> output
    ln_kernel<false><<<MM, 256>>>(res2, ln2_g, ln2_b, out, nullptr, nullptr);
}

// round 5
// speedup vs baseline: 4.2094x; 1.3338x over previous
#include <cuda_runtime.h>
#include <cuda_fp16.h>
#include <math.h>
#include <stdint.h>

// ---------------- problem constants ----------------
#define EE   1024
#define HID  4096
#define MM   8192            // B*N rows

// ---------------- scratch (device globals; no allocation) ----------------
__device__ __align__(128) __half g_xh [(size_t)MM * EE];
__device__ __align__(128) __half g_xl [(size_t)MM * EE];
__device__ __align__(128) __half g_wq [(size_t)3 * EE * EE];
__device__ __align__(128) __half g_wo [(size_t)EE * EE];
__device__ __align__(128) __half g_w1 [(size_t)HID * EE];
__device__ __align__(128) __half g_w2 [(size_t)EE * HID];
__device__ __align__(128) float  g_qkv[(size_t)MM * 3 * EE];
__device__ __align__(128) __half g_ah [(size_t)MM * EE];
__device__ __align__(128) __half g_al [(size_t)MM * EE];
__device__ __align__(128) float  g_res1[(size_t)MM * EE];
__device__ __align__(128) float  g_hf  [(size_t)MM * EE];
__device__ __align__(128) __half g_hh [(size_t)MM * EE];
__device__ __align__(128) __half g_hl [(size_t)MM * EE];
__device__ __align__(128) __half g_fh [(size_t)MM * HID];
__device__ __align__(128) __half g_fl [(size_t)MM * HID];
__device__ __align__(128) float  g_res2[(size_t)MM * EE];

// ---------------- helpers ----------------
__device__ __forceinline__ void split2(float v, __half& h, __half& l) {
    h = __float2half_rn(v);
    l = __float2half_rn(v - __half2float(h));
}
__device__ __forceinline__ void ldsm4(uint32_t& r0, uint32_t& r1, uint32_t& r2, uint32_t& r3,
                                      uint32_t a) {
    asm volatile("ldmatrix.sync.aligned.m8n8.x4.shared.b16 {%0,%1,%2,%3}, [%4];"
                 : "=r"(r0), "=r"(r1), "=r"(r2), "=r"(r3) : "r"(a));
}
__device__ __forceinline__ void mma16816(float* c, const uint32_t* a, const uint32_t* b) {
    asm volatile(
        "mma.sync.aligned.m16n8k16.row.col.f32.f16.f16.f32 "
        "{%0,%1,%2,%3}, {%4,%5,%6,%7}, {%8,%9}, {%0,%1,%2,%3};"
        : "+f"(c[0]), "+f"(c[1]), "+f"(c[2]), "+f"(c[3])
        : "r"(a[0]), "r"(a[1]), "r"(a[2]), "r"(a[3]), "r"(b[0]), "r"(b[1]));
}
__device__ __forceinline__ void cp16(uint32_t dst, const void* src) {
    asm volatile("cp.async.cg.shared.global [%0], [%1], 16;" :: "r"(dst), "l"(src));
}
__device__ __forceinline__ void cp_commit() { asm volatile("cp.async.commit_group;"); }
template <int N>
__device__ __forceinline__ void cp_wait() { asm volatile("cp.async.wait_group %0;" :: "n"(N)); }

// swizzled 16B-chunk offset within [rows x 64half] smem region (row-major 128B rows)
__device__ __forceinline__ uint32_t swoff(uint32_t r, uint32_t c) {
    return ((r << 3) + (c ^ (r & 7))) << 4;
}

// ---------------- hi/lo split (activations) ----------------
__global__ __launch_bounds__(256) void split_plain(
    const float* __restrict__ src, __half* __restrict__ hi,
    __half* __restrict__ lo, size_t total8)
{
    size_t idx = (size_t)blockIdx.x * blockDim.x + threadIdx.x;
    if (idx >= total8) return;
    const float4 v0 = reinterpret_cast<const float4*>(src)[idx * 2];
    const float4 v1 = reinterpret_cast<const float4*>(src)[idx * 2 + 1];
    float vv[8] = {v0.x, v0.y, v0.z, v0.w, v1.x, v1.y, v1.z, v1.w};
    __align__(16) __half hh[8], ll[8];
#pragma unroll
    for (int j = 0; j < 8; ++j) split2(vv[j], hh[j], ll[j]);
    reinterpret_cast<uint4*>(hi)[idx] = *reinterpret_cast<uint4*>(hh);
    reinterpret_cast<uint4*>(lo)[idx] = *reinterpret_cast<uint4*>(ll);
}

// ---------------- fp32 -> fp16 (weights, hi only) ----------------
__global__ __launch_bounds__(256) void to_half(
    const float* __restrict__ src, __half* __restrict__ dst, size_t total8)
{
    size_t idx = (size_t)blockIdx.x * blockDim.x + threadIdx.x;
    if (idx >= total8) return;
    const float4 v0 = reinterpret_cast<const float4*>(src)[idx * 2];
    const float4 v1 = reinterpret_cast<const float4*>(src)[idx * 2 + 1];
    __align__(16) __half hh[8];
    hh[0] = __float2half_rn(v0.x); hh[1] = __float2half_rn(v0.y);
    hh[2] = __float2half_rn(v0.z); hh[3] = __float2half_rn(v0.w);
    hh[4] = __float2half_rn(v1.x); hh[5] = __float2half_rn(v1.y);
    hh[6] = __float2half_rn(v1.z); hh[7] = __float2half_rn(v1.w);
    reinterpret_cast<uint4*>(dst)[idx] = *reinterpret_cast<uint4*>(hh);
}

// ---------------- fp16 2-term tensor-core GEMM: C[M,N] = (Ah+Al)[M,K] * B[N,K]^T ----------------
// Tile: 256x128, BK=64, 2 stages. 8 warps as 4(M) x 2(N), each 64x64.
// Stage layout: [Ah 32K][Al 32K][B 16K] = 80KB
// EPI 0: +bias -> Cf ; EPI 1: +bias,GELU -> Chi/Clo ; EPI 2: +bias+res -> Cf
#define STG_BYTES 81920
#define SMEM_GEMM (2 * STG_BYTES)

template <int EPI>
__global__ __launch_bounds__(256, 1) void gemm_mma(
    const __half* __restrict__ Ahi, const __half* __restrict__ Alo,
    const __half* __restrict__ B,
    const float* __restrict__ bias, const float* __restrict__ res,
    float* __restrict__ Cf, __half* __restrict__ Chi, __half* __restrict__ Clo,
    int M, int N, int K)
{
    extern __shared__ __align__(128) char smem[];
    const uint32_t sb = (uint32_t)__cvta_generic_to_shared(smem);

    const int tid  = threadIdx.x;
    const int lane = tid & 31;
    const int wid  = tid >> 5;
    const int wm   = wid & 3;        // 4 warps along M (64 rows each)
    const int wn   = wid >> 2;       // 2 warps along N (64 cols each)
    const int mblk = blockIdx.y * 256;
    const int nblk = blockIdx.x * 128;

    float acc[4][8][4];
#pragma unroll
    for (int i = 0; i < 4; ++i)
#pragma unroll
        for (int j = 0; j < 8; ++j)
#pragma unroll
            for (int q = 0; q < 4; ++q) acc[i][j][q] = 0.f;

    const int T = K >> 6;

    auto load_stage = [&](int s, int kc) {
        const uint32_t base = sb + s * STG_BYTES;
        const int k0 = kc * 64;
#pragma unroll
        for (int i = 0; i < 8; ++i) {               // A: 256 rows, hi+lo
            const int id  = tid + i * 256;
            const int row = id >> 3;
            const int c   = id & 7;
            const uint32_t so = swoff(row, c);
            const size_t ga = (size_t)(mblk + row) * K + k0 + c * 8;
            cp16(base + so,         Ahi + ga);
            cp16(base + 32768 + so, Alo + ga);
        }
#pragma unroll
        for (int i = 0; i < 4; ++i) {               // B: 128 rows, hi only
            const int id  = tid + i * 256;
            const int row = id >> 3;
            const int c   = id & 7;
            const uint32_t so = swoff(row, c);
            const size_t gb = (size_t)(nblk + row) * K + k0 + c * 8;
            cp16(base + 65536 + so, B + gb);
        }
    };

    load_stage(0, 0);
    cp_commit();

    for (int t = 0; t < T; ++t) {
        if (t + 1 < T) load_stage((t + 1) & 1, t + 1);
        cp_commit();
        cp_wait<1>();
        __syncthreads();

        const uint32_t stA = sb + (t & 1) * STG_BYTES;
        const uint32_t stB = stA + 65536;

#pragma unroll
        for (int ks = 0; ks < 4; ++ks) {
            uint32_t ah[4][4], al[4][4], b[8][2];
            const uint32_t arow = wm * 64 + (lane & 15);
            const uint32_t acol = ks * 2 + (lane >> 4);
#pragma unroll
            for (int mi = 0; mi < 4; ++mi) {
                const uint32_t off = swoff(arow + mi * 16, acol);
                ldsm4(ah[mi][0], ah[mi][1], ah[mi][2], ah[mi][3], stA + off);
                ldsm4(al[mi][0], al[mi][1], al[mi][2], al[mi][3], stA + 32768 + off);
            }
            const uint32_t brow = wn * 64 + (lane & 7) + ((lane >> 4) << 3);
            const uint32_t bcol = ks * 2 + ((lane >> 3) & 1);
#pragma unroll
            for (int pi = 0; pi < 4; ++pi) {
                const uint32_t off = swoff(brow + pi * 16, bcol);
                ldsm4(b[2 * pi][0], b[2 * pi][1], b[2 * pi + 1][0], b[2 * pi + 1][1],
                      stB + off);
            }
#pragma unroll
            for (int mi = 0; mi < 4; ++mi)
#pragma unroll
                for (int ni = 0; ni < 8; ++ni) mma16816(acc[mi][ni], ah[mi], b[ni]);
#pragma unroll
            for (int mi = 0; mi < 4; ++mi)
#pragma unroll
                for (int ni = 0; ni < 8; ++ni) mma16816(acc[mi][ni], al[mi], b[ni]);
        }
        __syncthreads();
    }
    cp_wait<0>();

    // -------- epilogue --------
#pragma unroll
    for (int mi = 0; mi < 4; ++mi) {
#pragma unroll
        for (int ni = 0; ni < 8; ++ni) {
            const int n = nblk + wn * 64 + ni * 8 + (lane & 3) * 2;
            const float b0 = bias[n], b1 = bias[n + 1];
            const int m0 = mblk + wm * 64 + mi * 16 + (lane >> 2);
#pragma unroll
            for (int half = 0; half < 2; ++half) {
                const int m = m0 + half * 8;
                float v0 = acc[mi][ni][half * 2 + 0] + b0;
                float v1 = acc[mi][ni][half * 2 + 1] + b1;
                if (EPI == 2) {
                    const float2 rv = *reinterpret_cast<const float2*>(res + (size_t)m * N + n);
                    v0 += rv.x; v1 += rv.y;
                }
                if (EPI == 0 || EPI == 2) {
                    *reinterpret_cast<float2*>(Cf + (size_t)m * N + n) = make_float2(v0, v1);
                } else {
                    v0 = 0.5f * v0 * (1.0f + erff(v0 * 0.70710678118654752f));
                    v1 = 0.5f * v1 * (1.0f + erff(v1 * 0.70710678118654752f));
                    __half2 h2, l2;
                    split2(v0, h2.x, l2.x);
                    split2(v1, h2.y, l2.y);
                    *reinterpret_cast<__half2*>(Chi + (size_t)m * N + n) = h2;
                    *reinterpret_cast<__half2*>(Clo + (size_t)m * N + n) = l2;
                }
            }
        }
    }
}

// ---------------- per-token head-softmax attention -> hi/lo fp16 output ----------------
__global__ __launch_bounds__(128) void attn_kernel(
    const float* __restrict__ qkv, __half* __restrict__ ahi, __half* __restrict__ alo)
{
    __shared__ float sq[3 * EE];
    __shared__ float sa[16][17];

    const int mrow = blockIdx.x;     // b*2048 + t
    const int b    = mrow >> 11;
    const int t    = mrow & 2047;
    const int tid  = threadIdx.x;

    const float4* src = reinterpret_cast<const float4*>(qkv + (size_t)mrow * (3 * EE));
    float4* ds = reinterpret_cast<float4*>(sq);
#pragma unroll
    for (int i = tid; i < 768; i += 128) ds[i] = src[i];
    __syncthreads();

#pragma unroll
    for (int e = tid; e < 256; e += 128) {
        const int i = e >> 4, j = e & 15;
        const float* qi = sq + i * 64;
        const float* kj = sq + EE + j * 64;
        float dot = 0.f;
#pragma unroll
        for (int d = 0; d < 64; ++d) dot += qi[d] * kj[d];
        sa[i][j] = dot * 0.03125f;   // / sqrt(E)=32
    }
    __syncthreads();

    if (tid < 16) {
        float mx = -1e30f;
#pragma unroll
        for (int j = 0; j < 16; ++j) mx = fmaxf(mx, sa[tid][j]);
        float ex[16], s = 0.f;
#pragma unroll
        for (int j = 0; j < 16; ++j) { ex[j] = expf(sa[tid][j] - mx); s += ex[j]; }
        const float inv = 1.0f / s;
#pragma unroll
        for (int j = 0; j < 16; ++j) sa[tid][j] = ex[j] * inv;
    }
    __syncthreads();

    const int i  = tid >> 3;
    const int db = (tid & 7) * 8;
    float o[8] = {0.f, 0.f, 0.f, 0.f, 0.f, 0.f, 0.f, 0.f};
#pragma unroll
    for (int j = 0; j < 16; ++j) {
        const float a = sa[i][j];
        const float* vj = sq + 2 * EE + j * 64 + db;
#pragma unroll
        for (int p = 0; p < 8; ++p) o[p] += a * vj[p];
    }
    // scrambled target: row = i*128 + t/16, col = (t%16)*64 + db
    const int m = b * 2048 + i * 128 + (t >> 4);
    const int c = ((t & 15) << 6) + db;
    __align__(16) __half hh[8], ll[8];
#pragma unroll
    for (int p = 0; p < 8; ++p) split2(o[p], hh[p], ll[p]);
    *reinterpret_cast<uint4*>(ahi + (size_t)m * EE + c) = *reinterpret_cast<uint4*>(hh);
    *reinterpret_cast<uint4*>(alo + (size_t)m * EE + c) = *reinterpret_cast<uint4*>(ll);
}

// ---------------- row LayerNorm (optionally also emits hi/lo fp16) ----------------
template <bool SPLIT>
__global__ __launch_bounds__(256) void ln_kernel(
    const float* __restrict__ in, const float* __restrict__ g, const float* __restrict__ b,
    float* __restrict__ outf, __half* __restrict__ ohi, __half* __restrict__ olo)
{
    __shared__ float red[8];
    __shared__ float s_mean, s_rstd;
    const int row = blockIdx.x;
    const int tid = threadIdx.x;

    const float4 v = reinterpret_cast<const float4*>(in + (size_t)row * EE)[tid];

    float s = v.x + v.y + v.z + v.w;
#pragma unroll
    for (int o = 16; o; o >>= 1) s += __shfl_xor_sync(0xffffffffu, s, o);
    if ((tid & 31) == 0) red[tid >> 5] = s;
    __syncthreads();
    if (tid == 0) {
        float tt = 0.f;
#pragma unroll
        for (int i = 0; i < 8; ++i) tt += red[i];
        s_mean = tt * (1.0f / 1024.0f);
    }
    __syncthreads();
    const float mean = s_mean;

    const float dx = v.x - mean, dy = v.y - mean, dz = v.z - mean, dw = v.w - mean;
    float sq = dx * dx + dy * dy + dz * dz + dw * dw;
#pragma unroll
    for (int o = 16; o; o >>= 1) sq += __shfl_xor_sync(0xffffffffu, sq, o);
    if ((tid & 31) == 0) red[tid >> 5] = sq;
    __syncthreads();
    if (tid == 0) {
        float tt = 0.f;
#pragma unroll
        for (int i = 0; i < 8; ++i) tt += red[i];
        s_rstd = rsqrtf(tt * (1.0f / 1024.0f) + 1e-5f);
    }
    __syncthreads();
    const float rstd = s_rstd;

    const float4 gg = reinterpret_cast<const float4*>(g)[tid];
    const float4 bb = reinterpret_cast<const float4*>(b)[tid];
    float4 o4;
    o4.x = dx * rstd * gg.x + bb.x;
    o4.y = dy * rstd * gg.y + bb.y;
    o4.z = dz * rstd * gg.z + bb.z;
    o4.w = dw * rstd * gg.w + bb.w;
    reinterpret_cast<float4*>(outf + (size_t)row * EE)[tid] = o4;

    if (SPLIT) {
        __align__(8) __half hh[4], ll[4];
        split2(o4.x, hh[0], ll[0]); split2(o4.y, hh[1], ll[1]);
        split2(o4.z, hh[2], ll[2]); split2(o4.w, hh[3], ll[3]);
        const size_t base = (size_t)row * EE + tid * 4;
        *reinterpret_cast<uint2*>(ohi + base) = *reinterpret_cast<uint2*>(hh);
        *reinterpret_cast<uint2*>(olo + base) = *reinterpret_cast<uint2*>(ll);
    }
}

// ---------------- launcher ----------------
extern "C" void kernel_launch(void* const* d_in, const int* in_sizes, int n_in,
                              void* d_out, int out_size)
{
    (void)in_sizes; (void)n_in; (void)out_size;
    const float* x     = (const float*)d_in[0];
    const float* Wqkv  = (const float*)d_in[1];
    const float* bqkv  = (const float*)d_in[2];
    const float* Wo    = (const float*)d_in[3];
    const float* bo    = (const float*)d_in[4];
    const float* ln1_g = (const float*)d_in[5];
    const float* ln1_b = (const float*)d_in[6];
    const float* W1    = (const float*)d_in[7];
    const float* bf1   = (const float*)d_in[8];
    const float* W2    = (const float*)d_in[9];
    const float* bf2   = (const float*)d_in[10];
    const float* ln2_g = (const float*)d_in[11];
    const float* ln2_b = (const float*)d_in[12];
    float* out = (float*)d_out;

    static bool attr_done = false;
    if (!attr_done) {
        cudaFuncSetAttribute(gemm_mma<0>, cudaFuncAttributeMaxDynamicSharedMemorySize, SMEM_GEMM);
        cudaFuncSetAttribute(gemm_mma<1>, cudaFuncAttributeMaxDynamicSharedMemorySize, SMEM_GEMM);
        cudaFuncSetAttribute(gemm_mma<2>, cudaFuncAttributeMaxDynamicSharedMemorySize, SMEM_GEMM);
        attr_done = true;
    }

    void* p;
    cudaGetSymbolAddress(&p, g_xh);   __half* xh = (__half*)p;
    cudaGetSymbolAddress(&p, g_xl);   __half* xl = (__half*)p;
    cudaGetSymbolAddress(&p, g_wq);   __half* wq = (__half*)p;
    cudaGetSymbolAddress(&p, g_wo);   __half* wo = (__half*)p;
    cudaGetSymbolAddress(&p, g_w1);   __half* w1 = (__half*)p;
    cudaGetSymbolAddress(&p, g_w2);   __half* w2 = (__half*)p;
    cudaGetSymbolAddress(&p, g_qkv);  float* qkv = (float*)p;
    cudaGetSymbolAddress(&p, g_ah);   __half* ah = (__half*)p;
    cudaGetSymbolAddress(&p, g_al);   __half* al = (__half*)p;
    cudaGetSymbolAddress(&p, g_res1); float* res1 = (float*)p;
    cudaGetSymbolAddress(&p, g_hf);   float* hf   = (float*)p;
    cudaGetSymbolAddress(&p, g_hh);   __half* hh = (__half*)p;
    cudaGetSymbolAddress(&p, g_hl);   __half* hl = (__half*)p;
    cudaGetSymbolAddress(&p, g_fh);   __half* fh = (__half*)p;
    cudaGetSymbolAddress(&p, g_fl);   __half* fl = (__half*)p;
    cudaGetSymbolAddress(&p, g_res2); float* res2 = (float*)p;

    // activation split (hi/lo) + weight conversion (hi only)
    split_plain<<<(MM * EE / 8 + 255) / 256, 256>>>(x, xh, xl, (size_t)MM * EE / 8);
    to_half<<<(3 * EE * EE / 8 + 255) / 256, 256>>>(Wqkv, wq, (size_t)3 * EE * EE / 8);
    to_half<<<(EE * EE / 8 + 255) / 256, 256>>>(Wo, wo, (size_t)EE * EE / 8);
    to_half<<<(HID * EE / 8 + 255) / 256, 256>>>(W1, w1, (size_t)HID * EE / 8);
    to_half<<<(EE * HID / 8 + 255) / 256, 256>>>(W2, w2, (size_t)EE * HID / 8);

    // 1) QKV projection
    gemm_mma<0><<<dim3(24, 32), 256, SMEM_GEMM>>>(xh, xl, wq, bqkv, nullptr,
                                                  qkv, nullptr, nullptr, MM, 3 * EE, EE);
    // 2) head-softmax attention + scrambled reshape
    attn_kernel<<<MM, 128>>>(qkv, ah, al);
    // 3) output projection + residual(x)
    gemm_mma<2><<<dim3(8, 32), 256, SMEM_GEMM>>>(ah, al, wo, bo, x,
                                                 res1, nullptr, nullptr, MM, EE, EE);
    // 4) LN1 -> h (fp32 + hi/lo)
    ln_kernel<true><<<MM, 256>>>(res1, ln1_g, ln1_b, hf, hh, hl);
    // 5) FFN up + GELU -> hi/lo
    gemm_mma<1><<<dim3(32, 32), 256, SMEM_GEMM>>>(hh, hl, w1, bf1, nullptr,
                                                  nullptr, fh, fl, MM, HID, EE);
    // 6) FFN down + residual(h)
    gemm_mma<2><<<dim3(8, 32), 256, SMEM_GEMM>>>(fh, fl, w2, bf2, hf,
                                                 res2, nullptr, nullptr, MM, EE, HID);
    // 7) LN2 -> output
    ln_kernel<false><<<MM, 256>>>(res2, ln2_g, ln2_b, out, nullptr, nullptr);
}

// round 6
// speedup vs baseline: 6.7704x; 1.6084x over previous
#include <cuda_runtime.h>
#include <cuda_fp16.h>
#include <math.h>
#include <stdint.h>

// ---------------- problem constants ----------------
#define EE   1024
#define HID  4096
#define MM   8192            // B*N rows

// ---------------- scratch (device globals; no allocation) ----------------
__device__ __align__(128) __half g_xh [(size_t)MM * EE];
__device__ __align__(128) __half g_wq [(size_t)3 * EE * EE];
__device__ __align__(128) __half g_wo [(size_t)EE * EE];
__device__ __align__(128) __half g_w1 [(size_t)HID * EE];
__device__ __align__(128) __half g_w2 [(size_t)EE * HID];
__device__ __align__(128) float  g_qkv[(size_t)MM * 3 * EE];
__device__ __align__(128) __half g_ah [(size_t)MM * EE];
__device__ __align__(128) float  g_res1[(size_t)MM * EE];
__device__ __align__(128) float  g_hf  [(size_t)MM * EE];
__device__ __align__(128) __half g_hh [(size_t)MM * EE];
__device__ __align__(128) __half g_fh [(size_t)MM * HID];
__device__ __align__(128) float  g_res2[(size_t)MM * EE];

// ---------------- helpers ----------------
__device__ __forceinline__ void ldsm4(uint32_t& r0, uint32_t& r1, uint32_t& r2, uint32_t& r3,
                                      uint32_t a) {
    asm volatile("ldmatrix.sync.aligned.m8n8.x4.shared.b16 {%0,%1,%2,%3}, [%4];"
                 : "=r"(r0), "=r"(r1), "=r"(r2), "=r"(r3) : "r"(a));
}
__device__ __forceinline__ void mma16816(float* c, const uint32_t* a, const uint32_t* b) {
    asm volatile(
        "mma.sync.aligned.m16n8k16.row.col.f32.f16.f16.f32 "
        "{%0,%1,%2,%3}, {%4,%5,%6,%7}, {%8,%9}, {%0,%1,%2,%3};"
        : "+f"(c[0]), "+f"(c[1]), "+f"(c[2]), "+f"(c[3])
        : "r"(a[0]), "r"(a[1]), "r"(a[2]), "r"(a[3]), "r"(b[0]), "r"(b[1]));
}
__device__ __forceinline__ void cp16(uint32_t dst, const void* src) {
    asm volatile("cp.async.cg.shared.global [%0], [%1], 16;" :: "r"(dst), "l"(src));
}
__device__ __forceinline__ void cp_commit() { asm volatile("cp.async.commit_group;"); }
template <int N>
__device__ __forceinline__ void cp_wait() { asm volatile("cp.async.wait_group %0;" :: "n"(N)); }

// swizzled 16B-chunk offset within [rows x 64half] smem region (row-major 128B rows)
__device__ __forceinline__ uint32_t swoff(uint32_t r, uint32_t c) {
    return ((r << 3) + (c ^ (r & 7))) << 4;
}

// ---------------- fp32 -> fp16 conversion ----------------
__global__ __launch_bounds__(256) void to_half(
    const float* __restrict__ src, __half* __restrict__ dst, size_t total8)
{
    size_t idx = (size_t)blockIdx.x * blockDim.x + threadIdx.x;
    if (idx >= total8) return;
    const float4 v0 = reinterpret_cast<const float4*>(src)[idx * 2];
    const float4 v1 = reinterpret_cast<const float4*>(src)[idx * 2 + 1];
    __align__(16) __half hh[8];
    hh[0] = __float2half_rn(v0.x); hh[1] = __float2half_rn(v0.y);
    hh[2] = __float2half_rn(v0.z); hh[3] = __float2half_rn(v0.w);
    hh[4] = __float2half_rn(v1.x); hh[5] = __float2half_rn(v1.y);
    hh[6] = __float2half_rn(v1.z); hh[7] = __float2half_rn(v1.w);
    reinterpret_cast<uint4*>(dst)[idx] = *reinterpret_cast<uint4*>(hh);
}

// ---------------- fp16 tensor-core GEMM: C[M,N] = A[M,K] * B[N,K]^T ----------------
// Tile: 256x128, BK=64, 3 stages. 8 warps as 4(M) x 2(N), each 64x64.
// Stage layout: [A 32K][B 16K] = 48KB
// EPI 0: +bias -> Cf ; EPI 1: +bias,GELU -> Ch fp16 ; EPI 2: +bias+res -> Cf
#define STG_BYTES 49152
#define SMEM_GEMM (3 * STG_BYTES)

template <int EPI>
__global__ __launch_bounds__(256, 1) void gemm_mma(
    const __half* __restrict__ A, const __half* __restrict__ B,
    const float* __restrict__ bias, const float* __restrict__ res,
    float* __restrict__ Cf, __half* __restrict__ Ch,
    int M, int N, int K)
{
    extern __shared__ __align__(128) char smem[];
    const uint32_t sb = (uint32_t)__cvta_generic_to_shared(smem);

    const int tid  = threadIdx.x;
    const int lane = tid & 31;
    const int wid  = tid >> 5;
    const int wm   = wid & 3;        // 4 warps along M (64 rows each)
    const int wn   = wid >> 2;       // 2 warps along N (64 cols each)
    const int mblk = blockIdx.y * 256;
    const int nblk = blockIdx.x * 128;

    float acc[4][8][4];
#pragma unroll
    for (int i = 0; i < 4; ++i)
#pragma unroll
        for (int j = 0; j < 8; ++j)
#pragma unroll
            for (int q = 0; q < 4; ++q) acc[i][j][q] = 0.f;

    const int T = K >> 6;

    auto load_stage = [&](int s, int kc) {
        const uint32_t base = sb + s * STG_BYTES;
        const int k0 = kc * 64;
#pragma unroll
        for (int i = 0; i < 8; ++i) {               // A: 256 rows
            const int id  = tid + i * 256;
            const int row = id >> 3;
            const int c   = id & 7;
            cp16(base + swoff(row, c), A + (size_t)(mblk + row) * K + k0 + c * 8);
        }
#pragma unroll
        for (int i = 0; i < 4; ++i) {               // B: 128 rows
            const int id  = tid + i * 256;
            const int row = id >> 3;
            const int c   = id & 7;
            cp16(base + 32768 + swoff(row, c), B + (size_t)(nblk + row) * K + k0 + c * 8);
        }
    };

    load_stage(0, 0); cp_commit();
    load_stage(1, 1); cp_commit();

    for (int t = 0; t < T; ++t) {
        if (t + 2 < T) load_stage((t + 2) % 3, t + 2);
        cp_commit();                 // empty groups at tail keep accounting uniform
        cp_wait<2>();
        __syncthreads();

        const uint32_t stA = sb + (t % 3) * STG_BYTES;
        const uint32_t stB = stA + 32768;

#pragma unroll
        for (int ks = 0; ks < 4; ++ks) {
            uint32_t a[4][4], b[8][2];
            const uint32_t arow = wm * 64 + (lane & 15);
            const uint32_t acol = ks * 2 + (lane >> 4);
#pragma unroll
            for (int mi = 0; mi < 4; ++mi) {
                const uint32_t off = swoff(arow + mi * 16, acol);
                ldsm4(a[mi][0], a[mi][1], a[mi][2], a[mi][3], stA + off);
            }
            const uint32_t brow = wn * 64 + (lane & 7) + ((lane >> 4) << 3);
            const uint32_t bcol = ks * 2 + ((lane >> 3) & 1);
#pragma unroll
            for (int pi = 0; pi < 4; ++pi) {
                const uint32_t off = swoff(brow + pi * 16, bcol);
                ldsm4(b[2 * pi][0], b[2 * pi][1], b[2 * pi + 1][0], b[2 * pi + 1][1],
                      stB + off);
            }
#pragma unroll
            for (int mi = 0; mi < 4; ++mi)
#pragma unroll
                for (int ni = 0; ni < 8; ++ni) mma16816(acc[mi][ni], a[mi], b[ni]);
        }
        __syncthreads();
    }
    cp_wait<0>();

    // -------- epilogue --------
#pragma unroll
    for (int mi = 0; mi < 4; ++mi) {
#pragma unroll
        for (int ni = 0; ni < 8; ++ni) {
            const int n = nblk + wn * 64 + ni * 8 + (lane & 3) * 2;
            const float b0 = bias[n], b1 = bias[n + 1];
            const int m0 = mblk + wm * 64 + mi * 16 + (lane >> 2);
#pragma unroll
            for (int half = 0; half < 2; ++half) {
                const int m = m0 + half * 8;
                float v0 = acc[mi][ni][half * 2 + 0] + b0;
                float v1 = acc[mi][ni][half * 2 + 1] + b1;
                if (EPI == 2) {
                    const float2 rv = *reinterpret_cast<const float2*>(res + (size_t)m * N + n);
                    v0 += rv.x; v1 += rv.y;
                }
                if (EPI == 0 || EPI == 2) {
                    *reinterpret_cast<float2*>(Cf + (size_t)m * N + n) = make_float2(v0, v1);
                } else {
                    v0 = 0.5f * v0 * (1.0f + erff(v0 * 0.70710678118654752f));
                    v1 = 0.5f * v1 * (1.0f + erff(v1 * 0.70710678118654752f));
                    __half2 h2;
                    h2.x = __float2half_rn(v0);
                    h2.y = __float2half_rn(v1);
                    *reinterpret_cast<__half2*>(Ch + (size_t)m * N + n) = h2;
                }
            }
        }
    }
}

// ---------------- per-token head-softmax attention -> fp16 output ----------------
__global__ __launch_bounds__(128) void attn_kernel(
    const float* __restrict__ qkv, __half* __restrict__ ahi)
{
    __shared__ float sq[3 * EE];
    __shared__ float sa[16][17];

    const int mrow = blockIdx.x;     // b*2048 + t
    const int b    = mrow >> 11;
    const int t    = mrow & 2047;
    const int tid  = threadIdx.x;

    const float4* src = reinterpret_cast<const float4*>(qkv + (size_t)mrow * (3 * EE));
    float4* ds = reinterpret_cast<float4*>(sq);
#pragma unroll
    for (int i = tid; i < 768; i += 128) ds[i] = src[i];
    __syncthreads();

#pragma unroll
    for (int e = tid; e < 256; e += 128) {
        const int i = e >> 4, j = e & 15;
        const float* qi = sq + i * 64;
        const float* kj = sq + EE + j * 64;
        float dot = 0.f;
#pragma unroll
        for (int d = 0; d < 64; ++d) dot += qi[d] * kj[d];
        sa[i][j] = dot * 0.03125f;   // / sqrt(E)=32
    }
    __syncthreads();

    if (tid < 16) {
        float mx = -1e30f;
#pragma unroll
        for (int j = 0; j < 16; ++j) mx = fmaxf(mx, sa[tid][j]);
        float ex[16], s = 0.f;
#pragma unroll
        for (int j = 0; j < 16; ++j) { ex[j] = expf(sa[tid][j] - mx); s += ex[j]; }
        const float inv = 1.0f / s;
#pragma unroll
        for (int j = 0; j < 16; ++j) sa[tid][j] = ex[j] * inv;
    }
    __syncthreads();

    const int i  = tid >> 3;
    const int db = (tid & 7) * 8;
    float o[8] = {0.f, 0.f, 0.f, 0.f, 0.f, 0.f, 0.f, 0.f};
#pragma unroll
    for (int j = 0; j < 16; ++j) {
        const float a = sa[i][j];
        const float* vj = sq + 2 * EE + j * 64 + db;
#pragma unroll
        for (int p = 0; p < 8; ++p) o[p] += a * vj[p];
    }
    // scrambled target: row = i*128 + t/16, col = (t%16)*64 + db
    const int m = b * 2048 + i * 128 + (t >> 4);
    const int c = ((t & 15) << 6) + db;
    __align__(16) __half hh[8];
#pragma unroll
    for (int p = 0; p < 8; ++p) hh[p] = __float2half_rn(o[p]);
    *reinterpret_cast<uint4*>(ahi + (size_t)m * EE + c) = *reinterpret_cast<uint4*>(hh);
}

// ---------------- row LayerNorm (optionally also emits fp16) ----------------
template <bool EMIT_HALF>
__global__ __launch_bounds__(256) void ln_kernel(
    const float* __restrict__ in, const float* __restrict__ g, const float* __restrict__ b,
    float* __restrict__ outf, __half* __restrict__ oh)
{
    __shared__ float red[8];
    __shared__ float s_mean, s_rstd;
    const int row = blockIdx.x;
    const int tid = threadIdx.x;

    const float4 v = reinterpret_cast<const float4*>(in + (size_t)row * EE)[tid];

    float s = v.x + v.y + v.z + v.w;
#pragma unroll
    for (int o = 16; o; o >>= 1) s += __shfl_xor_sync(0xffffffffu, s, o);
    if ((tid & 31) == 0) red[tid >> 5] = s;
    __syncthreads();
    if (tid == 0) {
        float tt = 0.f;
#pragma unroll
        for (int i = 0; i < 8; ++i) tt += red[i];
        s_mean = tt * (1.0f / 1024.0f);
    }
    __syncthreads();
    const float mean = s_mean;

    const float dx = v.x - mean, dy = v.y - mean, dz = v.z - mean, dw = v.w - mean;
    float sq = dx * dx + dy * dy + dz * dz + dw * dw;
#pragma unroll
    for (int o = 16; o; o >>= 1) sq += __shfl_xor_sync(0xffffffffu, sq, o);
    if ((tid & 31) == 0) red[tid >> 5] = sq;
    __syncthreads();
    if (tid == 0) {
        float tt = 0.f;
#pragma unroll
        for (int i = 0; i < 8; ++i) tt += red[i];
        s_rstd = rsqrtf(tt * (1.0f / 1024.0f) + 1e-5f);
    }
    __syncthreads();
    const float rstd = s_rstd;

    const float4 gg = reinterpret_cast<const float4*>(g)[tid];
    const float4 bb = reinterpret_cast<const float4*>(b)[tid];
    float4 o4;
    o4.x = dx * rstd * gg.x + bb.x;
    o4.y = dy * rstd * gg.y + bb.y;
    o4.z = dz * rstd * gg.z + bb.z;
    o4.w = dw * rstd * gg.w + bb.w;
    reinterpret_cast<float4*>(outf + (size_t)row * EE)[tid] = o4;

    if (EMIT_HALF) {
        __align__(8) __half hh[4];
        hh[0] = __float2half_rn(o4.x); hh[1] = __float2half_rn(o4.y);
        hh[2] = __float2half_rn(o4.z); hh[3] = __float2half_rn(o4.w);
        *reinterpret_cast<uint2*>(oh + (size_t)row * EE + tid * 4) =
            *reinterpret_cast<uint2*>(hh);
    }
}

// ---------------- launcher ----------------
extern "C" void kernel_launch(void* const* d_in, const int* in_sizes, int n_in,
                              void* d_out, int out_size)
{
    (void)in_sizes; (void)n_in; (void)out_size;
    const float* x     = (const float*)d_in[0];
    const float* Wqkv  = (const float*)d_in[1];
    const float* bqkv  = (const float*)d_in[2];
    const float* Wo    = (const float*)d_in[3];
    const float* bo    = (const float*)d_in[4];
    const float* ln1_g = (const float*)d_in[5];
    const float* ln1_b = (const float*)d_in[6];
    const float* W1    = (const float*)d_in[7];
    const float* bf1   = (const float*)d_in[8];
    const float* W2    = (const float*)d_in[9];
    const float* bf2   = (const float*)d_in[10];
    const float* ln2_g = (const float*)d_in[11];
    const float* ln2_b = (const float*)d_in[12];
    float* out = (float*)d_out;

    static bool attr_done = false;
    if (!attr_done) {
        cudaFuncSetAttribute(gemm_mma<0>, cudaFuncAttributeMaxDynamicSharedMemorySize, SMEM_GEMM);
        cudaFuncSetAttribute(gemm_mma<1>, cudaFuncAttributeMaxDynamicSharedMemorySize, SMEM_GEMM);
        cudaFuncSetAttribute(gemm_mma<2>, cudaFuncAttributeMaxDynamicSharedMemorySize, SMEM_GEMM);
        attr_done = true;
    }

    void* p;
    cudaGetSymbolAddress(&p, g_xh);   __half* xh = (__half*)p;
    cudaGetSymbolAddress(&p, g_wq);   __half* wq = (__half*)p;
    cudaGetSymbolAddress(&p, g_wo);   __half* wo = (__half*)p;
    cudaGetSymbolAddress(&p, g_w1);   __half* w1 = (__half*)p;
    cudaGetSymbolAddress(&p, g_w2);   __half* w2 = (__half*)p;
    cudaGetSymbolAddress(&p, g_qkv);  float* qkv = (float*)p;
    cudaGetSymbolAddress(&p, g_ah);   __half* ah = (__half*)p;
    cudaGetSymbolAddress(&p, g_res1); float* res1 = (float*)p;
    cudaGetSymbolAddress(&p, g_hf);   float* hf   = (float*)p;
    cudaGetSymbolAddress(&p, g_hh);   __half* hh = (__half*)p;
    cudaGetSymbolAddress(&p, g_fh);   __half* fh = (__half*)p;
    cudaGetSymbolAddress(&p, g_res2); float* res2 = (float*)p;

    // fp16 conversions
    to_half<<<(MM * EE / 8 + 255) / 256, 256>>>(x, xh, (size_t)MM * EE / 8);
    to_half<<<(3 * EE * EE / 8 + 255) / 256, 256>>>(Wqkv, wq, (size_t)3 * EE * EE / 8);
    to_half<<<(EE * EE / 8 + 255) / 256, 256>>>(Wo, wo, (size_t)EE * EE / 8);
    to_half<<<(HID * EE / 8 + 255) / 256, 256>>>(W1, w1, (size_t)HID * EE / 8);
    to_half<<<(EE * HID / 8 + 255) / 256, 256>>>(W2, w2, (size_t)EE * HID / 8);

    // 1) QKV projection
    gemm_mma<0><<<dim3(24, 32), 256, SMEM_GEMM>>>(xh, wq, bqkv, nullptr,
                                                  qkv, nullptr, MM, 3 * EE, EE);
    // 2) head-softmax attention + scrambled reshape
    attn_kernel<<<MM, 128>>>(qkv, ah);
    // 3) output projection + residual(x)
    gemm_mma<2><<<dim3(8, 32), 256, SMEM_GEMM>>>(ah, wo, bo, x,
                                                 res1, nullptr, MM, EE, EE);
    // 4) LN1 -> h (fp32 + fp16)
    ln_kernel<true><<<MM, 256>>>(res1, ln1_g, ln1_b, hf, hh);
    // 5) FFN up + GELU -> fp16
    gemm_mma<1><<<dim3(32, 32), 256, SMEM_GEMM>>>(hh, w1, bf1, nullptr,
                                                  nullptr, fh, MM, HID, EE);
    // 6) FFN down + residual(h)
    gemm_mma<2><<<dim3(8, 32), 256, SMEM_GEMM>>>(fh, w2, bf2, hf,
                                                 res2, nullptr, MM, EE, HID);
    // 7) LN2 -> output
    ln_kernel<false><<<MM, 256>>>(res2, ln2_g, ln2_b, out, nullptr);
}